// round 16
// baseline (speedup 1.0000x reference)
#include <cuda_runtime.h>

// Problem constants (static per init_kwargs)
#define N_IMG 8
#define CIN   64
#define H     112
#define W     112
#define HW    12544          // H*W, patches per image (stride 1, pad 1)
#define DPAT  576            // Cin * K * K
#define COUT  64
#define MEM   1025           // memo table size

// Persistent-kernel geometry: 148 SMs x 4 co-resident blocks (guaranteed by
// __launch_bounds__(256,4): regs <= 64, smem 11.2KB/block) -> grid barrier safe.
#define NBLK  592
#define NTHR  256

// Phase A tiling: 14x14 tiles, 16x16 halo == exactly 1 halo pixel per thread.
#define TL    14
#define HL    16
#define TPD   8              // 112/14 tiles per dim
#define NTILE (N_IMG * TPD * TPD)   // 512 (<= NBLK: one tile per block)

// Phase B: 4-consecutive-bin clusters per item (one weight pass serves 4 bins)
#define NCL    257           // ceil(MEM/4)
#define NITEMB (N_IMG * NCL) // 2056

// Scratch (device globals — no allocation allowed).
// g_first: encoded first patch enc = HW - p (0 == empty). Zero at load;
// phase C re-zeros each replay -> graph is self-restoring.
__device__ int      g_bins[N_IMG * HW];
__device__ int      g_first[N_IMG * MEM];
__device__ float    g_rep[N_IMG * MEM * COUT];
__device__ unsigned g_barctr[2];
__device__ unsigned g_bargen[2];

// ---------------------------------------------------------------------------
// df64 helpers (all __fadd_rn: fast-math-proof). hi+lo == exact to ~2^-48.
// Accumulation ORDER is kept identical to the previously-passing kernel, so
// the computed bins are bit-identical.
// ---------------------------------------------------------------------------
__device__ __forceinline__ void two_sum(float a, float b, float& s, float& e) {
    s = __fadd_rn(a, b);
    float bb   = __fadd_rn(s, -a);
    float err1 = __fadd_rn(a, -__fadd_rn(s, -bb));
    float err2 = __fadd_rn(b, -bb);
    e = __fadd_rn(err1, err2);
}
__device__ __forceinline__ void df_add(float ah, float al, float bh, float bl,
                                       float& rh, float& rl) {
    float s, e;
    two_sum(ah, bh, s, e);
    e  = __fadd_rn(e, __fadd_rn(al, bl));
    rh = __fadd_rn(s, e);
    rl = __fadd_rn(e, __fadd_rn(s, -rh));
}
__device__ __forceinline__ void df_acc(float& hi, float& lo, float x) {
    float s, e;
    two_sum(hi, x, s, e);
    lo = __fadd_rn(lo, e);
    hi = s;
}

// ---------------------------------------------------------------------------
// Device-wide barrier: sense-generation. Release: every thread __threadfence()
// (gpu scope -> CCTL.IVALL, flushes/invalidates L1) before tid0 arrives.
// Acquire: tid0 spins on gen (volatile, L2), then all threads fence again.
// ctr self-resets before gen bump -> replay-safe; gen is monotonic (wrap-safe).
// ---------------------------------------------------------------------------
__device__ __forceinline__ void grid_barrier(int i) {
    __threadfence();
    __syncthreads();
    if (threadIdx.x == 0) {
        unsigned gen = *(volatile unsigned*)&g_bargen[i];
        if (atomicAdd(&g_barctr[i], 1u) == NBLK - 1) {
            g_barctr[i] = 0;
            __threadfence();
            atomicAdd(&g_bargen[i], 1u);
        } else {
            while (*(volatile unsigned*)&g_bargen[i] == gen) { }
        }
    }
    __syncthreads();
    __threadfence();
}

// ---------------------------------------------------------------------------
// The megakernel: Phase A (bins) | barrier | Phase B (rep rows) | barrier |
// Phase C (broadcast scatter + table reset).
// ---------------------------------------------------------------------------
__global__ void __launch_bounds__(NTHR, 4)
k_mega(const float* __restrict__ fmap, const float* __restrict__ weight,
       const float* __restrict__ bias, float* __restrict__ out) {
    __shared__ float sh_hi[HL * HL];
    __shared__ float sh_lo[HL * HL];
    __shared__ float sp[4][DPAT];

    int tid = threadIdx.x;
    int bid = blockIdx.x;

    // ===================== Phase A: quantized-bin assignment ================
    if (bid < NTILE) {
        int n  = bid >> 6;            // / (TPD*TPD)
        int t  = bid & 63;
        int ty = t >> 3, tx = t & 7;
        int gy0 = ty * TL - 1;        // halo origin (can be -1)
        int gx0 = tx * TL - 1;
        const float* fb = fmap + n * CIN * HW;

        // df64 channel sum: exactly one halo pixel per thread (256 == HL*HL)
        {
            int hy = tid >> 4, hx = tid & 15;
            int gy = gy0 + hy, gx = gx0 + hx;
            float h0 = 0.f, l0 = 0.f, h1 = 0.f, l1 = 0.f;
            float h2 = 0.f, l2 = 0.f, h3 = 0.f, l3 = 0.f;
            if ((unsigned)gy < H && (unsigned)gx < W) {
                const float* p = fb + gy * W + gx;
#pragma unroll
                for (int cg = 0; cg < 4; ++cg) {       // 4 groups of 16 channels
                    float v[16];
#pragma unroll
                    for (int i = 0; i < 16; ++i)
                        v[i] = __ldg(p + (cg * 16 + i) * HW);
#pragma unroll
                    for (int i = 0; i < 16; i += 4) {
                        df_acc(h0, l0, v[i + 0]);
                        df_acc(h1, l1, v[i + 1]);
                        df_acc(h2, l2, v[i + 2]);
                        df_acc(h3, l3, v[i + 3]);
                    }
                }
            }
            float ah, al, bh, bl, rh, rl;
            df_add(h0, l0, h1, l1, ah, al);
            df_add(h2, l2, h3, l3, bh, bl);
            df_add(ah, al, bh, bl, rh, rl);
            sh_hi[tid] = rh;
            sh_lo[tid] = rl;
        }
        __syncthreads();

        if (tid < TL * TL) {
            int ly = tid / TL, lx = tid - ly * TL;
            int gy = ty * TL + ly, gx = tx * TL + lx;

            float shi = 0.f, slo = 0.f;
#pragma unroll
            for (int dy = 0; dy < 3; ++dy)
#pragma unroll
                for (int dx = 0; dx < 3; ++dx) {
                    int idx = (ly + dy) * HL + (lx + dx);
                    float rh, rl;
                    df_add(shi, slo, sh_hi[idx], sh_lo[idx], rh, rl);
                    shi = rh; slo = rl;
                }

            // bit-exact replica of the reference quantization
            float q  = __fmul_rn(__fdiv_rn(shi, 576.0f), 100.0f);
            int summ = __float2int_rz(q);
            int bin  = summ + 512;
            bin = bin < 0 ? 0 : (bin > MEM - 1 ? MEM - 1 : bin);

            int p = gy * W + gx;
            g_bins[n * HW + p] = bin;
            atomicMax(&g_first[n * MEM + bin], HW - p);  // min-p == max-(HW-p)
        }
    }

    grid_barrier(0);

    // ===================== Phase B: representative GEMM rows ================
    for (int it = bid; it < NITEMB; it += NBLK) {
        int n  = it / NCL;
        int c0 = (it - n * NCL) * 4;          // first bin of this cluster

        int  fp[4];
        bool act[4];
        bool any = false;
#pragma unroll
        for (int j = 0; j < 4; ++j) {
            int b = c0 + j;
            int e = (b < MEM) ? __ldcg(&g_first[n * MEM + b]) : 0;
            act[j] = (e > 0);
            fp[j]  = HW - e;
            any |= act[j];
        }
        if (!any) continue;                   // block-uniform branch

        const float* fb = fmap + n * CIN * HW;
#pragma unroll
        for (int j = 0; j < 4; ++j) {
            if (act[j]) {
                int y = fp[j] / W, x = fp[j] - (fp[j] / W) * W;
                for (int i = tid; i < DPAT; i += NTHR) {
                    int c = i / 9, r = i - c * 9;
                    int kh = r / 3, kw = r - kh * 3;
                    int yy = y + kh - 1, xx = x + kw - 1;
                    float v = 0.f;
                    if ((unsigned)yy < H && (unsigned)xx < W)
                        v = __ldg(fb + c * HW + yy * W + xx);
                    sp[j][i] = v;
                }
            } else {
                for (int i = tid; i < DPAT; i += NTHR) sp[j][i] = 0.f;
            }
        }
        __syncthreads();

        // thread = (cout, quarter-of-D); one weight pass serves all 4 bins
        int cout = tid >> 2, part = tid & 3;
        const float4* w4 = (const float4*)(weight + cout * DPAT + part * 144);
        const float4* s0 = (const float4*)(&sp[0][part * 144]);
        const float4* s1 = (const float4*)(&sp[1][part * 144]);
        const float4* s2 = (const float4*)(&sp[2][part * 144]);
        const float4* s3 = (const float4*)(&sp[3][part * 144]);
        float a0 = 0.f, a1 = 0.f, a2 = 0.f, a3 = 0.f;
#pragma unroll 6
        for (int d = 0; d < 36; ++d) {
            float4 w = __ldg(&w4[d]);
            float4 v0 = s0[d], v1 = s1[d], v2 = s2[d], v3 = s3[d];
            a0 = fmaf(v0.x, w.x, a0); a0 = fmaf(v0.y, w.y, a0);
            a0 = fmaf(v0.z, w.z, a0); a0 = fmaf(v0.w, w.w, a0);
            a1 = fmaf(v1.x, w.x, a1); a1 = fmaf(v1.y, w.y, a1);
            a1 = fmaf(v1.z, w.z, a1); a1 = fmaf(v1.w, w.w, a1);
            a2 = fmaf(v2.x, w.x, a2); a2 = fmaf(v2.y, w.y, a2);
            a2 = fmaf(v2.z, w.z, a2); a2 = fmaf(v2.w, w.w, a2);
            a3 = fmaf(v3.x, w.x, a3); a3 = fmaf(v3.y, w.y, a3);
            a3 = fmaf(v3.z, w.z, a3); a3 = fmaf(v3.w, w.w, a3);
        }
        a0 += __shfl_xor_sync(0xffffffffu, a0, 1);
        a0 += __shfl_xor_sync(0xffffffffu, a0, 2);
        a1 += __shfl_xor_sync(0xffffffffu, a1, 1);
        a1 += __shfl_xor_sync(0xffffffffu, a1, 2);
        a2 += __shfl_xor_sync(0xffffffffu, a2, 1);
        a2 += __shfl_xor_sync(0xffffffffu, a2, 2);
        a3 += __shfl_xor_sync(0xffffffffu, a3, 1);
        a3 += __shfl_xor_sync(0xffffffffu, a3, 2);

        if (part == 0) {
            float bs = __ldg(&bias[cout]);
            if (act[0]) g_rep[(n * MEM + c0 + 0) * COUT + cout] = a0 + bs;
            if (act[1]) g_rep[(n * MEM + c0 + 1) * COUT + cout] = a1 + bs;
            if (act[2]) g_rep[(n * MEM + c0 + 2) * COUT + cout] = a2 + bs;
            if (act[3]) g_rep[(n * MEM + c0 + 3) * COUT + cout] = a3 + bs;
        }
        __syncthreads();                      // sp reused next iteration
    }

    grid_barrier(1);

    // ===================== Phase C: broadcast scatter + table reset =========
    int gidx = bid * NTHR + tid;              // 0 .. 151551
    if (gidx < N_IMG * MEM) g_first[gidx] = 0;   // self-restore for replay

    if (gidx < N_IMG * HW) {                  // 100352 items: (4px, 16-cout)
        int quarter = gidx / (N_IMG * HW / 4);   // 0..3 (25088 groups each)
        int grp     = gidx - quarter * (N_IMG * HW / 4);
        int pix0    = grp * 4;                // never crosses image boundary
        int n  = pix0 / HW;
        int p0 = pix0 - n * HW;

        int4 b4 = __ldcg((const int4*)(g_bins + pix0));
        const float* repb = g_rep + n * MEM * COUT + quarter * 16;
        float* ob = out + (n * COUT + quarter * 16) * HW + p0;

        if (b4.x == b4.y && b4.x == b4.z && b4.x == b4.w) {
            // uniform-bin fast path: splat 16 channel values
            const float4* r4 = (const float4*)(repb + b4.x * COUT);
#pragma unroll
            for (int i = 0; i < 4; ++i) {
                float4 v = __ldg(&r4[i]);
                *(float4*)(ob + (4 * i + 0) * HW) = make_float4(v.x, v.x, v.x, v.x);
                *(float4*)(ob + (4 * i + 1) * HW) = make_float4(v.y, v.y, v.y, v.y);
                *(float4*)(ob + (4 * i + 2) * HW) = make_float4(v.z, v.z, v.z, v.z);
                *(float4*)(ob + (4 * i + 3) * HW) = make_float4(v.w, v.w, v.w, v.w);
            }
        } else {
            const float* r0 = repb + b4.x * COUT;
            const float* r1 = repb + b4.y * COUT;
            const float* r2 = repb + b4.z * COUT;
            const float* r3 = repb + b4.w * COUT;
#pragma unroll
            for (int c = 0; c < 16; ++c) {
                float4 o = make_float4(__ldg(r0 + c), __ldg(r1 + c),
                                       __ldg(r2 + c), __ldg(r3 + c));
                *(float4*)(ob + c * HW) = o;
            }
        }
    }
}

// ---------------------------------------------------------------------------
extern "C" void kernel_launch(void* const* d_in, const int* in_sizes, int n_in,
                              void* d_out, int out_size) {
    const float* fmap   = (const float*)d_in[0];   // [8,64,112,112]
    const float* weight = (const float*)d_in[1];   // [64,576]
    const float* bias   = (const float*)d_in[2];   // [64]
    float* out = (float*)d_out;                    // [8,64,112,112]
    (void)in_sizes; (void)n_in; (void)out_size;

    k_mega<<<NBLK, NTHR>>>(fmap, weight, bias, out);
}